// round 10
// baseline (speedup 1.0000x reference)
#include <cuda_runtime.h>
#include <math.h>
#include <stdint.h>

// ---------------------------------------------------------------------------
// GATNE forward v5:
//   k_scan   : one CTA, two stable partitions (idx<NU ; type)
//   k_gather : warp per (b,t), streaming neighbor gather+sum -> g_nsum4
//   k_trans  : type-partitioned transform + attention; 4 rows/warp
//   k_gemm4  : BM=64 x BN=200, 320 thr, 8x5 thread tile; user class fused
//              normalize; text class K-split x7 -> partials
//   k_reduce : sum 7 partials per text row, normalize, write
// ---------------------------------------------------------------------------

#define EMB       200
#define EMBU      20
#define TEXT_DIM  768
#define USER_DIM  32
#define NSLOT     10
#define B_MAX     4096
#define NCHUNK    7            // text K-split: 21 tiles = 7 chunks x 3

// ------------------------- device scratch ----------------------------------
__device__ int    g_rowmap[B_MAX];   // partition by idx<NU (users first)
__device__ int    g_tmap[B_MAX];     // partition by type (type0 first)
__device__ int    g_nuser;
__device__ int    g_ntype0;
__device__ float  g_agg[B_MAX * 40];
__device__ float4 g_nsum4[B_MAX * 2 * (TEXT_DIM / 4)];   // [B][2][192] float4
__device__ float  g_part[(size_t)NCHUNK * B_MAX * EMB];  // text partials

// ------------------------- scan: two partitions, one pass -------------------
__global__ __launch_bounds__(1024, 1) void k_scan(
    const int* __restrict__ indices, const int* __restrict__ types,
    int B, int NU)
{
    __shared__ int wsU[32], wsT[32];
    int tid = threadIdx.x;
    int lane = tid & 31, w = tid >> 5;
    int b0 = tid * 4;

    int idxv[4], tyv[4];
    int cu = 0, ct = 0;
#pragma unroll
    for (int j = 0; j < 4; j++) {
        int b = b0 + j;
        if (b < B) {
            idxv[j] = indices[b];
            tyv[j]  = types[b];
            cu += (idxv[j] < NU);
            ct += (tyv[j] == 0);
        }
    }
    int xu = cu, xt = ct;
    for (int o = 1; o < 32; o <<= 1) {
        int yu = __shfl_up_sync(0xffffffffu, xu, o);
        int yt = __shfl_up_sync(0xffffffffu, xt, o);
        if (lane >= o) { xu += yu; xt += yt; }
    }
    if (lane == 31) { wsU[w] = xu; wsT[w] = xt; }
    __syncthreads();
    int baseU = 0, baseT = 0, totU = 0, totT = 0;
    for (int i = 0; i < 32; i++) {
        if (i < w) { baseU += wsU[i]; baseT += wsT[i]; }
        totU += wsU[i]; totT += wsT[i];
    }
    int uRun = (xu - cu) + baseU;
    int tRun = (xt - ct) + baseT;
#pragma unroll
    for (int j = 0; j < 4; j++) {
        int b = b0 + j;
        if (b >= B) break;
        if (idxv[j] < NU) g_rowmap[uRun++] = b;
        else              g_rowmap[totU + (b - uRun)] = b;
        if (tyv[j] == 0)  g_tmap[tRun++] = b;
        else              g_tmap[totT + (b - tRun)] = b;
    }
    if (tid == 0) { g_nuser = totU; g_ntype0 = totT; }
}

// ------------------------- gather: warp per (b,t) ----------------------------
__global__ __launch_bounds__(256) void k_gather(
    const int*   __restrict__ train_types,
    const int*   __restrict__ node_neigh,
    const float* __restrict__ neigh_features,
    int B)
{
    int tid  = threadIdx.x;
    int wid  = tid >> 5;
    int lane = tid & 31;
    int gw   = blockIdx.x * 8 + wid;
    int b    = gw >> 1;
    int t    = gw & 1;
    if (b >= B) return;

    int ty = train_types[b];
    int nn_l = 0;
    if (lane < NSLOT)
        nn_l = node_neigh[(size_t)(b * 2 + t) * NSLOT + lane];

    const float4* nf4 = (const float4*)neigh_features;
    float4* dst = g_nsum4 + (size_t)(b * 2 + t) * 192;

    if (ty == 1) {
#pragma unroll 2
        for (int c = 0; c < 6; c++) {
            int k4 = c * 32 + lane;
            float4 acc = make_float4(0.f, 0.f, 0.f, 0.f);
#pragma unroll
            for (int s = 0; s < NSLOT; s++) {
                int idx = __shfl_sync(0xffffffffu, nn_l, s);
                float4 v = nf4[(size_t)idx * 192 + k4];
                acc.x += v.x; acc.y += v.y; acc.z += v.z; acc.w += v.w;
            }
            dst[k4] = acc;
        }
    } else {
        float4 acc = make_float4(0.f, 0.f, 0.f, 0.f);
#pragma unroll
        for (int s = 0; s < NSLOT; s++) {
            int idx = __shfl_sync(0xffffffffu, nn_l, s);
            if (lane < 8) {
                float4 v = nf4[(size_t)idx * 192 + lane];
                acc.x += v.x; acc.y += v.y; acc.z += v.z; acc.w += v.w;
            }
        }
        if (lane < 8) dst[lane] = acc;
    }
}

// ------------------------- transform + attention -----------------------------
// Grid: [0,T) type-0 tiles, [T,2T) type-1 (T = ceil(B/32)).
// 32 rows per CTA, 8 warps, 4 rows per warp (shared U reads).
__global__ __launch_bounds__(256, 1) void k_trans(
    const float* __restrict__ tweet_u,
    const float* __restrict__ user_u,
    const float* __restrict__ s1,
    const float* __restrict__ s2,
    int B, int T)
{
    extern __shared__ float sm[];
    float* U2  = sm;                        // [2][F][20]
    float* nte = U2 + 2 * TEXT_DIM * EMBU;  // [32][40]
    int*  srow = (int*)(nte + 32 * 40);     // [32]

    int tid  = threadIdx.x;
    int wid  = tid >> 5;
    int lane = tid & 31;

    int ty   = (blockIdx.x >= T) ? 1 : 0;
    int tile = ty ? (blockIdx.x - T) : blockIdx.x;
    int n0   = g_ntype0;
    int base = ty ? n0 : 0;
    int cnt  = ty ? (B - n0) : n0;
    int m0   = tile * 32;
    if (m0 >= cnt) return;

    int F = ty ? TEXT_DIM : USER_DIM;

    {
        int cnt4 = (2 * F * EMBU) / 4;
        const float4* src = (const float4*)(ty ? tweet_u : user_u);
        float4* d = (float4*)U2;
        for (int i = tid; i < cnt4; i += 256) d[i] = src[i];
    }
    if (tid < 32) {
        int mm = m0 + tid; if (mm > cnt - 1) mm = cnt - 1;
        srow[tid] = g_tmap[base + mm];
    }
    __syncthreads();

    // warp w: rows 4w .. 4w+3
    {
        int i0 = 4 * wid;
        int br[4];
#pragma unroll
        for (int r = 0; r < 4; r++) br[r] = srow[i0 + r];
        const float* ns = (const float*)g_nsum4;

        for (int t = 0; t < 2; t++) {
            float acc[4][EMBU];
#pragma unroll
            for (int r = 0; r < 4; r++)
#pragma unroll
                for (int u = 0; u < EMBU; u++) acc[r][u] = 0.f;
            const float* nsr[4];
#pragma unroll
            for (int r = 0; r < 4; r++)
                nsr[r] = ns + (size_t)(br[r] * 2 + t) * TEXT_DIM;
            const float* Ut = U2 + (size_t)t * F * EMBU;

            for (int k = lane; k < F; k += 32) {
                float a0 = nsr[0][k], a1 = nsr[1][k];
                float a2 = nsr[2][k], a3 = nsr[3][k];
                const float4* Urow = (const float4*)(Ut + k * EMBU);
#pragma unroll
                for (int q = 0; q < 5; q++) {
                    float4 uv = Urow[q];
                    acc[0][q*4+0] += a0 * uv.x; acc[1][q*4+0] += a1 * uv.x;
                    acc[2][q*4+0] += a2 * uv.x; acc[3][q*4+0] += a3 * uv.x;
                    acc[0][q*4+1] += a0 * uv.y; acc[1][q*4+1] += a1 * uv.y;
                    acc[2][q*4+1] += a2 * uv.y; acc[3][q*4+1] += a3 * uv.y;
                    acc[0][q*4+2] += a0 * uv.z; acc[1][q*4+2] += a1 * uv.z;
                    acc[2][q*4+2] += a2 * uv.z; acc[3][q*4+2] += a3 * uv.z;
                    acc[0][q*4+3] += a0 * uv.w; acc[1][q*4+3] += a1 * uv.w;
                    acc[2][q*4+3] += a2 * uv.w; acc[3][q*4+3] += a3 * uv.w;
                }
            }
#pragma unroll
            for (int r = 0; r < 4; r++)
#pragma unroll
                for (int u = 0; u < EMBU; u++) {
                    float v = acc[r][u];
                    for (int o = 16; o; o >>= 1)
                        v += __shfl_xor_sync(0xffffffffu, v, o);
                    if (lane == 0) nte[(i0 + r) * 40 + t * EMBU + u] = v;
                }
        }
    }
    __syncthreads();

    const float* S1 = s1 + ty * (EMBU * EMBU);
    const float* S2 = s2 + ty * EMBU;
    for (int g = wid; g < 32; g += 8) {
        if (m0 + g >= cnt) continue;
        int b = srow[g];
        float sc[2];
#pragma unroll
        for (int t = 0; t < 2; t++) {
            float h = 0.f;
            if (lane < EMBU) {
#pragma unroll
                for (int u = 0; u < EMBU; u++)
                    h += nte[g * 40 + t * EMBU + u] * S1[u * EMBU + lane];
                h = tanhf(h) * S2[lane];
            }
            for (int o = 16; o; o >>= 1) h += __shfl_xor_sync(0xffffffffu, h, o);
            sc[t] = h;
        }
        float m  = fmaxf(sc[0], sc[1]);
        float e0 = expf(sc[0] - m);
        float e1 = expf(sc[1] - m);
        float inv = 1.f / (e0 + e1);
        float a0 = e0 * inv, a1 = e1 * inv;
        for (int l = lane; l < 40; l += 32) {
            float v = 0.f;
            if ((l / EMBU) == ty) {
                int u = l - (l / EMBU) * EMBU;
                v = a0 * nte[g * 40 + u] + a1 * nte[g * 40 + EMBU + u];
            }
            g_agg[(size_t)b * 40 + l] = v;
        }
    }
}

// ------------------------- GEMM v4: BM=64 x BN=200, 320 threads --------------
// thread tile 8x5; grid: [0,utiles) user (tiles 0-1, fused normalize),
// [utiles, utiles*(1+NCHUNK)) text chunks (3 k-tiles each) -> partials
__global__ __launch_bounds__(320, 2) void k_gemm4(
    float* __restrict__ out,
    const int*   __restrict__ indices,
    const float* __restrict__ user_features,
    const float* __restrict__ text_features,
    const float* __restrict__ user_embed,
    const float* __restrict__ text_embed,
    const float* __restrict__ trans_w,
    int B, int NU, int utiles)
{
    __shared__ __align__(16) float As[40][68];
    __shared__ __align__(16) float Bs[40][EMB];
    __shared__ float ssP[64][41];
    __shared__ float snrm[64];
    __shared__ int   srow[64], sidx[64];

    int bx = blockIdx.x;
    int cls, tm, chunk, kt0, ntk;
    if (bx < utiles) { cls = 0; tm = bx; chunk = 0; kt0 = 0; ntk = 2; }
    else {
        int r = bx - utiles;
        tm = r / NCHUNK; chunk = r - tm * NCHUNK;
        cls = 1; kt0 = chunk * 3; ntk = 3;
    }
    int nuser = g_nuser;
    int base  = cls ? nuser : 0;
    int cnt   = cls ? (B - nuser) : nuser;
    int m0    = tm * 64;
    if (m0 >= cnt) return;

    int tid = threadIdx.x;
    if (tid < 64) {
        int mm = m0 + tid; if (mm > cnt - 1) mm = cnt - 1;
        int b = g_rowmap[base + mm];
        srow[tid] = b;
        sidx[tid] = indices[b];
    }
    __syncthreads();

    int rg = tid / 40;             // 0..7  (8 rows each)
    int cg = tid - rg * 40;        // 0..39 (5 cols each)

    float acc[8][5];
#pragma unroll
    for (int i = 0; i < 8; i++)
#pragma unroll
        for (int j = 0; j < 5; j++) acc[i][j] = 0.f;

    for (int t = 0; t < ntk; t++) {
        int k0 = (kt0 + t) * 40;
        // A tile: 64 rows x 40 k
        for (int i = tid; i < 64 * 40; i += 320) {
            int m = i & 63, k = i >> 6;
            int kk = k0 + k;
            int b = srow[m], idx = sidx[m];
            float v;
            if (kk < USER_DIM)
                v = (idx < NU) ? user_features[(size_t)idx * USER_DIM + kk] : 0.f;
            else if (kk < 72)
                v = g_agg[(size_t)b * 40 + (kk - USER_DIM)];
            else
                v = (idx < NU) ? 0.f
                               : text_features[(size_t)(idx - NU) * TEXT_DIM + (kk - 72)];
            As[k][m] = v;
        }
        // B tile: 40 x 200, float4
        for (int i = tid; i < 40 * (EMB / 4); i += 320) {
            int k  = i / (EMB / 4);
            int j4 = i - k * (EMB / 4);
            int kk = k0 + k;
            const float* src;
            if (kk < USER_DIM)      src = user_embed + (size_t)kk * EMB;
            else if (kk < 72)       src = trans_w + (size_t)(kk - USER_DIM) * EMB;
            else                    src = text_embed + (size_t)(kk - 72) * EMB;
            ((float4*)&Bs[k][0])[j4] = ((const float4*)src)[j4];
        }
        __syncthreads();

#pragma unroll 5
        for (int k = 0; k < 40; k++) {
            float4 av0 = *(const float4*)&As[k][rg * 8];
            float4 av1 = *(const float4*)&As[k][rg * 8 + 4];
            float a[8] = {av0.x, av0.y, av0.z, av0.w,
                          av1.x, av1.y, av1.z, av1.w};
            float bb[5];
#pragma unroll
            for (int j = 0; j < 5; j++) bb[j] = Bs[k][cg * 5 + j];
#pragma unroll
            for (int i = 0; i < 8; i++)
#pragma unroll
                for (int j = 0; j < 5; j++)
                    acc[i][j] += a[i] * bb[j];
        }
        __syncthreads();
    }

    if (cls == 0) {
#pragma unroll
        for (int r = 0; r < 8; r++) {
            float s = 0.f;
#pragma unroll
            for (int j = 0; j < 5; j++) s += acc[r][j] * acc[r][j];
            ssP[rg * 8 + r][cg] = s;
        }
        __syncthreads();
        if (tid < 64) {
            float s = 0.f;
            for (int c = 0; c < 40; c++) s += ssP[tid][c];
            snrm[tid] = 1.f / fmaxf(sqrtf(s), 1e-12f);
        }
        __syncthreads();
#pragma unroll
        for (int r = 0; r < 8; r++) {
            int m = rg * 8 + r;
            if (m0 + m < cnt) {
                float sc = snrm[m];
                float* o = out + (size_t)srow[m] * EMB + cg * 5;
#pragma unroll
                for (int j = 0; j < 5; j++) o[j] = acc[r][j] * sc;
            }
        }
    } else {
        float* pb = g_part + (size_t)chunk * B_MAX * EMB;
#pragma unroll
        for (int r = 0; r < 8; r++) {
            int m = rg * 8 + r;
            int mr = m0 + m;
            if (mr < cnt) {
                float* p = pb + (size_t)mr * EMB + cg * 5;
#pragma unroll
                for (int j = 0; j < 5; j++) p[j] = acc[r][j];
            }
        }
    }
}

// ------------------------- reduce partials + normalize -----------------------
__global__ __launch_bounds__(256) void k_reduce(float* __restrict__ out, int B)
{
    __shared__ float ws[8];
    int i = blockIdx.x;
    int nuser = g_nuser;
    int ntext = B - nuser;
    if (i >= ntext) return;
    int b = g_rowmap[nuser + i];
    int tid = threadIdx.x;

    float v = 0.f;
    if (tid < EMB) {
#pragma unroll
        for (int c = 0; c < NCHUNK; c++)
            v += g_part[(size_t)c * B_MAX * EMB + (size_t)i * EMB + tid];
    }
    float s = v * v;
    for (int o = 16; o; o >>= 1) s += __shfl_xor_sync(0xffffffffu, s, o);
    if ((tid & 31) == 0) ws[tid >> 5] = s;
    __syncthreads();
    float tot = 0.f;
#pragma unroll
    for (int w = 0; w < 8; w++) tot += ws[w];
    float sc = 1.f / fmaxf(sqrtf(tot), 1e-12f);
    if (tid < EMB) out[(size_t)b * EMB + tid] = v * sc;
}

// ------------------------- launch ------------------------------------------
extern "C" void kernel_launch(void* const* d_in, const int* in_sizes, int n_in,
                              void* d_out, int out_size)
{
    const int*   train_types    = (const int*)d_in[1];
    const int*   node_neigh     = (const int*)d_in[2];
    const int*   indices        = (const int*)d_in[3];
    const float* user_features  = (const float*)d_in[4];
    const float* text_features  = (const float*)d_in[5];
    const float* neigh_features = (const float*)d_in[6];
    const float* text_embed     = (const float*)d_in[7];
    const float* user_embed     = (const float*)d_in[8];
    const float* tweet_u        = (const float*)d_in[9];
    const float* user_u         = (const float*)d_in[10];
    const float* trans_w        = (const float*)d_in[11];
    const float* s1             = (const float*)d_in[12];
    const float* s2             = (const float*)d_in[13];

    int B  = in_sizes[3];
    int NU = in_sizes[4] / USER_DIM;
    float* out = (float*)d_out;

    const int trans_smem = (2 * TEXT_DIM * EMBU + 32 * 40) * 4 + 32 * 4;
    cudaFuncSetAttribute(k_trans, cudaFuncAttributeMaxDynamicSharedMemorySize,
                         trans_smem);

    int gwarps = B * 2;
    k_gather<<<(gwarps + 7) / 8, 256>>>(train_types, node_neigh,
                                        neigh_features, B);

    k_scan<<<1, 1024>>>(indices, train_types, B, NU);

    int T = (B + 31) / 32;
    k_trans<<<2 * T, 256, trans_smem>>>(tweet_u, user_u, s1, s2, B, T);

    int utiles = (B + 63) / 64;
    k_gemm4<<<utiles * (1 + NCHUNK), 320>>>(out, indices, user_features,
                                            text_features, user_embed,
                                            text_embed, trans_w, B, NU, utiles);

    k_reduce<<<B, 256>>>(out, B);
}

// round 11
// speedup vs baseline: 1.0531x; 1.0531x over previous
#include <cuda_runtime.h>
#include <math.h>
#include <stdint.h>

// ---------------------------------------------------------------------------
// GATNE forward v6:
//   k_scan   : one CTA, two stable partitions (idx<NU ; type)
//   k_gather : warp per (b,t), streaming neighbor gather+sum -> g_nsum4
//   k_trans  : type-partitioned transform + attention; 4 rows/warp
//   k_gemm5  : BM=64 x BN=200, 320 thr, 8x5 tile, cp.async DOUBLE-BUFFERED
//              A (m-major) + B tiles; user class fused normalize; text class
//              K-split x7 -> partials
//   k_reduce : sum 7 partials per text row, normalize, write
// ---------------------------------------------------------------------------

#define EMB       200
#define EMBU      20
#define TEXT_DIM  768
#define USER_DIM  32
#define NSLOT     10
#define B_MAX     4096
#define NCHUNK    7            // text K-split: 21 tiles = 7 chunks x 3

// gemm smem layout (floats)
#define AM_LD     44
#define AM_BUF    (64 * AM_LD)            // 2816
#define OFF_AM    0
#define OFF_BS    (2 * AM_BUF)            // 5632
#define BS_BUF    (40 * EMB)              // 8000
#define OFF_SNRM  (OFF_BS + 2 * BS_BUF)   // 21632
#define OFF_SROW  (OFF_SNRM + 64)         // 21696
#define OFF_SIDX  (OFF_SROW + 64)         // 21760
#define GEMM_SMEM_FLOATS (OFF_SIDX + 64)  // 21824

// ------------------------- device scratch ----------------------------------
__device__ int    g_rowmap[B_MAX];
__device__ int    g_tmap[B_MAX];
__device__ int    g_nuser;
__device__ int    g_ntype0;
__device__ float  g_agg[B_MAX * 40];
__device__ float4 g_nsum4[B_MAX * 2 * (TEXT_DIM / 4)];
__device__ float  g_part[(size_t)NCHUNK * B_MAX * EMB];

// ------------------------- cp.async helpers ---------------------------------
__device__ __forceinline__ void cp16(void* dst, const void* src)
{
    uint32_t d = (uint32_t)__cvta_generic_to_shared(dst);
    asm volatile("cp.async.cg.shared.global [%0], [%1], 16;\n"
                 :: "r"(d), "l"(src));
}
__device__ __forceinline__ void cp_commit()
{
    asm volatile("cp.async.commit_group;\n");
}
template<int N> __device__ __forceinline__ void cp_wait()
{
    asm volatile("cp.async.wait_group %0;\n" :: "n"(N));
}

// ------------------------- scan --------------------------------------------
__global__ __launch_bounds__(1024, 1) void k_scan(
    const int* __restrict__ indices, const int* __restrict__ types,
    int B, int NU)
{
    __shared__ int wsU[32], wsT[32];
    int tid = threadIdx.x;
    int lane = tid & 31, w = tid >> 5;
    int b0 = tid * 4;

    int idxv[4], tyv[4];
    int cu = 0, ct = 0;
#pragma unroll
    for (int j = 0; j < 4; j++) {
        int b = b0 + j;
        if (b < B) {
            idxv[j] = indices[b];
            tyv[j]  = types[b];
            cu += (idxv[j] < NU);
            ct += (tyv[j] == 0);
        }
    }
    int xu = cu, xt = ct;
    for (int o = 1; o < 32; o <<= 1) {
        int yu = __shfl_up_sync(0xffffffffu, xu, o);
        int yt = __shfl_up_sync(0xffffffffu, xt, o);
        if (lane >= o) { xu += yu; xt += yt; }
    }
    if (lane == 31) { wsU[w] = xu; wsT[w] = xt; }
    __syncthreads();
    int baseU = 0, baseT = 0, totU = 0, totT = 0;
    for (int i = 0; i < 32; i++) {
        if (i < w) { baseU += wsU[i]; baseT += wsT[i]; }
        totU += wsU[i]; totT += wsT[i];
    }
    int uRun = (xu - cu) + baseU;
    int tRun = (xt - ct) + baseT;
#pragma unroll
    for (int j = 0; j < 4; j++) {
        int b = b0 + j;
        if (b >= B) break;
        if (idxv[j] < NU) g_rowmap[uRun++] = b;
        else              g_rowmap[totU + (b - uRun)] = b;
        if (tyv[j] == 0)  g_tmap[tRun++] = b;
        else              g_tmap[totT + (b - tRun)] = b;
    }
    if (tid == 0) { g_nuser = totU; g_ntype0 = totT; }
}

// ------------------------- gather ------------------------------------------
__global__ __launch_bounds__(256) void k_gather(
    const int*   __restrict__ train_types,
    const int*   __restrict__ node_neigh,
    const float* __restrict__ neigh_features,
    int B)
{
    int tid  = threadIdx.x;
    int wid  = tid >> 5;
    int lane = tid & 31;
    int gw   = blockIdx.x * 8 + wid;
    int b    = gw >> 1;
    int t    = gw & 1;
    if (b >= B) return;

    int ty = train_types[b];
    int nn_l = 0;
    if (lane < NSLOT)
        nn_l = node_neigh[(size_t)(b * 2 + t) * NSLOT + lane];

    const float4* nf4 = (const float4*)neigh_features;
    float4* dst = g_nsum4 + (size_t)(b * 2 + t) * 192;

    if (ty == 1) {
#pragma unroll 2
        for (int c = 0; c < 6; c++) {
            int k4 = c * 32 + lane;
            float4 acc = make_float4(0.f, 0.f, 0.f, 0.f);
#pragma unroll
            for (int s = 0; s < NSLOT; s++) {
                int idx = __shfl_sync(0xffffffffu, nn_l, s);
                float4 v = nf4[(size_t)idx * 192 + k4];
                acc.x += v.x; acc.y += v.y; acc.z += v.z; acc.w += v.w;
            }
            dst[k4] = acc;
        }
    } else {
        float4 acc = make_float4(0.f, 0.f, 0.f, 0.f);
#pragma unroll
        for (int s = 0; s < NSLOT; s++) {
            int idx = __shfl_sync(0xffffffffu, nn_l, s);
            if (lane < 8) {
                float4 v = nf4[(size_t)idx * 192 + lane];
                acc.x += v.x; acc.y += v.y; acc.z += v.z; acc.w += v.w;
            }
        }
        if (lane < 8) dst[lane] = acc;
    }
}

// ------------------------- transform + attention -----------------------------
__global__ __launch_bounds__(256, 1) void k_trans(
    const float* __restrict__ tweet_u,
    const float* __restrict__ user_u,
    const float* __restrict__ s1,
    const float* __restrict__ s2,
    int B, int T)
{
    extern __shared__ float sm[];
    float* U2  = sm;
    float* nte = U2 + 2 * TEXT_DIM * EMBU;
    int*  srow = (int*)(nte + 32 * 40);

    int tid  = threadIdx.x;
    int wid  = tid >> 5;
    int lane = tid & 31;

    int ty   = (blockIdx.x >= T) ? 1 : 0;
    int tile = ty ? (blockIdx.x - T) : blockIdx.x;
    int n0   = g_ntype0;
    int base = ty ? n0 : 0;
    int cnt  = ty ? (B - n0) : n0;
    int m0   = tile * 32;
    if (m0 >= cnt) return;

    int F = ty ? TEXT_DIM : USER_DIM;

    {
        int cnt4 = (2 * F * EMBU) / 4;
        const float4* src = (const float4*)(ty ? tweet_u : user_u);
        float4* d = (float4*)U2;
        for (int i = tid; i < cnt4; i += 256) d[i] = src[i];
    }
    if (tid < 32) {
        int mm = m0 + tid; if (mm > cnt - 1) mm = cnt - 1;
        srow[tid] = g_tmap[base + mm];
    }
    __syncthreads();

    {
        int i0 = 4 * wid;
        int br[4];
#pragma unroll
        for (int r = 0; r < 4; r++) br[r] = srow[i0 + r];
        const float* ns = (const float*)g_nsum4;

        for (int t = 0; t < 2; t++) {
            float acc[4][EMBU];
#pragma unroll
            for (int r = 0; r < 4; r++)
#pragma unroll
                for (int u = 0; u < EMBU; u++) acc[r][u] = 0.f;
            const float* nsr[4];
#pragma unroll
            for (int r = 0; r < 4; r++)
                nsr[r] = ns + (size_t)(br[r] * 2 + t) * TEXT_DIM;
            const float* Ut = U2 + (size_t)t * F * EMBU;

            for (int k = lane; k < F; k += 32) {
                float a0 = nsr[0][k], a1 = nsr[1][k];
                float a2 = nsr[2][k], a3 = nsr[3][k];
                const float4* Urow = (const float4*)(Ut + k * EMBU);
#pragma unroll
                for (int q = 0; q < 5; q++) {
                    float4 uv = Urow[q];
                    acc[0][q*4+0] += a0 * uv.x; acc[1][q*4+0] += a1 * uv.x;
                    acc[2][q*4+0] += a2 * uv.x; acc[3][q*4+0] += a3 * uv.x;
                    acc[0][q*4+1] += a0 * uv.y; acc[1][q*4+1] += a1 * uv.y;
                    acc[2][q*4+1] += a2 * uv.y; acc[3][q*4+1] += a3 * uv.y;
                    acc[0][q*4+2] += a0 * uv.z; acc[1][q*4+2] += a1 * uv.z;
                    acc[2][q*4+2] += a2 * uv.z; acc[3][q*4+2] += a3 * uv.z;
                    acc[0][q*4+3] += a0 * uv.w; acc[1][q*4+3] += a1 * uv.w;
                    acc[2][q*4+3] += a2 * uv.w; acc[3][q*4+3] += a3 * uv.w;
                }
            }
#pragma unroll
            for (int r = 0; r < 4; r++)
#pragma unroll
                for (int u = 0; u < EMBU; u++) {
                    float v = acc[r][u];
                    for (int o = 16; o; o >>= 1)
                        v += __shfl_xor_sync(0xffffffffu, v, o);
                    if (lane == 0) nte[(i0 + r) * 40 + t * EMBU + u] = v;
                }
        }
    }
    __syncthreads();

    const float* S1 = s1 + ty * (EMBU * EMBU);
    const float* S2 = s2 + ty * EMBU;
    for (int g = wid; g < 32; g += 8) {
        if (m0 + g >= cnt) continue;
        int b = srow[g];
        float sc[2];
#pragma unroll
        for (int t = 0; t < 2; t++) {
            float h = 0.f;
            if (lane < EMBU) {
#pragma unroll
                for (int u = 0; u < EMBU; u++)
                    h += nte[g * 40 + t * EMBU + u] * S1[u * EMBU + lane];
                h = tanhf(h) * S2[lane];
            }
            for (int o = 16; o; o >>= 1) h += __shfl_xor_sync(0xffffffffu, h, o);
            sc[t] = h;
        }
        float m  = fmaxf(sc[0], sc[1]);
        float e0 = expf(sc[0] - m);
        float e1 = expf(sc[1] - m);
        float inv = 1.f / (e0 + e1);
        float a0 = e0 * inv, a1 = e1 * inv;
        for (int l = lane; l < 40; l += 32) {
            float v = 0.f;
            if ((l / EMBU) == ty) {
                int u = l - (l / EMBU) * EMBU;
                v = a0 * nte[g * 40 + u] + a1 * nte[g * 40 + EMBU + u];
            }
            g_agg[(size_t)b * 40 + l] = v;
        }
    }
}

// ------------------------- GEMM v5: cp.async double-buffered -----------------
__global__ __launch_bounds__(320, 2) void k_gemm5(
    float* __restrict__ out,
    const int*   __restrict__ indices,
    const float* __restrict__ user_features,
    const float* __restrict__ text_features,
    const float* __restrict__ user_embed,
    const float* __restrict__ text_embed,
    const float* __restrict__ trans_w,
    int B, int NU, int utiles)
{
    extern __shared__ float sm[];
    float* Am   = sm + OFF_AM;      // [2][64][AM_LD]  m-major
    float* Bsm  = sm + OFF_BS;      // [2][40][EMB]
    float* snrm = sm + OFF_SNRM;
    int*   srow = (int*)(sm + OFF_SROW);
    int*   sidx = (int*)(sm + OFF_SIDX);

    int bx = blockIdx.x;
    int cls, tm, chunk, kt0, ntk;
    if (bx < utiles) { cls = 0; tm = bx; chunk = 0; kt0 = 0; ntk = 2; }
    else {
        int r = bx - utiles;
        tm = r / NCHUNK; chunk = r - tm * NCHUNK;
        cls = 1; kt0 = chunk * 3; ntk = 3;
    }
    int nuser = g_nuser;
    int base  = cls ? nuser : 0;
    int cnt   = cls ? (B - nuser) : nuser;
    int m0    = tm * 64;
    if (m0 >= cnt) return;

    int tid = threadIdx.x;
    if (tid < 64) {
        int mm = m0 + tid; if (mm > cnt - 1) mm = cnt - 1;
        int b = g_rowmap[base + mm];
        srow[tid] = b;
        sidx[tid] = indices[b];
    }
    __syncthreads();

    // ---- tile loaders (cp.async) ----
    // A tile: 64 rows x 40 k as Am[m][k], 10 float4 per row
    auto loadA = [&](int kt, int buf) {
        float* dstb = Am + buf * AM_BUF;
        int k0 = kt * 40;
#pragma unroll
        for (int ii = 0; ii < 2; ii++) {
            int i = tid + ii * 320;
            int m  = i / 10;
            int j4 = i - m * 10;
            int kk = k0 + j4 * 4;
            float* d = dstb + m * AM_LD + j4 * 4;
            int b = srow[m], idx = sidx[m];
            if (cls == 0) {
                if (kk < USER_DIM)
                    cp16(d, user_features + (size_t)idx * USER_DIM + kk);
                else if (kk < 72)
                    cp16(d, g_agg + (size_t)b * 40 + (kk - USER_DIM));
                else
                    *(float4*)d = make_float4(0.f, 0.f, 0.f, 0.f);
            } else {
                if (kk < USER_DIM)
                    *(float4*)d = make_float4(0.f, 0.f, 0.f, 0.f);
                else if (kk < 72)
                    cp16(d, g_agg + (size_t)b * 40 + (kk - USER_DIM));
                else
                    cp16(d, text_features + (size_t)(idx - NU) * TEXT_DIM + (kk - 72));
            }
        }
    };
    // B tile: 40 k-rows x 200, 50 float4 per row
    auto loadB = [&](int kt, int buf) {
        float* dstb = Bsm + buf * BS_BUF;
        int k0 = kt * 40;
        for (int i = tid; i < 2000; i += 320) {
            int k  = i / 50;
            int j4 = i - k * 50;
            int kk = k0 + k;
            const float* src;
            if (kk < USER_DIM)      src = user_embed + (size_t)kk * EMB;
            else if (kk < 72)       src = trans_w + (size_t)(kk - USER_DIM) * EMB;
            else                    src = text_embed + (size_t)(kk - 72) * EMB;
            cp16(dstb + k * EMB + j4 * 4, src + j4 * 4);
        }
    };

    int rg = tid / 40;
    int cg = tid - rg * 40;

    float acc[8][5];
#pragma unroll
    for (int i = 0; i < 8; i++)
#pragma unroll
        for (int j = 0; j < 5; j++) acc[i][j] = 0.f;

    // prologue: prefetch tile 0
    loadA(kt0, 0); loadB(kt0, 0); cp_commit();

    for (int t = 0; t < ntk; t++) {
        int buf = t & 1;
        if (t + 1 < ntk) {
            loadA(kt0 + t + 1, buf ^ 1);
            loadB(kt0 + t + 1, buf ^ 1);
            cp_commit();
            cp_wait<1>();
        } else {
            cp_wait<0>();
        }
        __syncthreads();

        const float* A = Am + buf * AM_BUF + rg * 8 * AM_LD;
        const float* Bt = Bsm + buf * BS_BUF + cg * 5;
#pragma unroll 5
        for (int k2 = 0; k2 < 20; k2++) {
            int k = 2 * k2;
            float2 a2[8];
#pragma unroll
            for (int i = 0; i < 8; i++)
                a2[i] = *(const float2*)(A + i * AM_LD + k);
            float b0[5], b1[5];
#pragma unroll
            for (int j = 0; j < 5; j++) {
                b0[j] = Bt[k * EMB + j];
                b1[j] = Bt[(k + 1) * EMB + j];
            }
#pragma unroll
            for (int i = 0; i < 8; i++)
#pragma unroll
                for (int j = 0; j < 5; j++)
                    acc[i][j] += a2[i].x * b0[j] + a2[i].y * b1[j];
        }
        __syncthreads();
    }

    if (cls == 0) {
        // fused normalize; reuse Am region as ssP[64][41]
        float* ssP = Am;
#pragma unroll
        for (int r = 0; r < 8; r++) {
            float s = 0.f;
#pragma unroll
            for (int j = 0; j < 5; j++) s += acc[r][j] * acc[r][j];
            ssP[(rg * 8 + r) * 41 + cg] = s;
        }
        __syncthreads();
        if (tid < 64) {
            float s = 0.f;
            for (int c = 0; c < 40; c++) s += ssP[tid * 41 + c];
            snrm[tid] = 1.f / fmaxf(sqrtf(s), 1e-12f);
        }
        __syncthreads();
#pragma unroll
        for (int r = 0; r < 8; r++) {
            int m = rg * 8 + r;
            if (m0 + m < cnt) {
                float sc = snrm[m];
                float* o = out + (size_t)srow[m] * EMB + cg * 5;
#pragma unroll
                for (int j = 0; j < 5; j++) o[j] = acc[r][j] * sc;
            }
        }
    } else {
        float* pb = g_part + (size_t)chunk * B_MAX * EMB;
#pragma unroll
        for (int r = 0; r < 8; r++) {
            int m = rg * 8 + r;
            int mr = m0 + m;
            if (mr < cnt) {
                float* p = pb + (size_t)mr * EMB + cg * 5;
#pragma unroll
                for (int j = 0; j < 5; j++) p[j] = acc[r][j];
            }
        }
    }
}

// ------------------------- reduce partials + normalize -----------------------
__global__ __launch_bounds__(256) void k_reduce(float* __restrict__ out, int B)
{
    __shared__ float ws[8];
    int i = blockIdx.x;
    int nuser = g_nuser;
    int ntext = B - nuser;
    if (i >= ntext) return;
    int b = g_rowmap[nuser + i];
    int tid = threadIdx.x;

    float v = 0.f;
    if (tid < EMB) {
#pragma unroll
        for (int c = 0; c < NCHUNK; c++)
            v += g_part[(size_t)c * B_MAX * EMB + (size_t)i * EMB + tid];
    }
    float s = v * v;
    for (int o = 16; o; o >>= 1) s += __shfl_xor_sync(0xffffffffu, s, o);
    if ((tid & 31) == 0) ws[tid >> 5] = s;
    __syncthreads();
    float tot = 0.f;
#pragma unroll
    for (int w = 0; w < 8; w++) tot += ws[w];
    float sc = 1.f / fmaxf(sqrtf(tot), 1e-12f);
    if (tid < EMB) out[(size_t)b * EMB + tid] = v * sc;
}

// ------------------------- launch ------------------------------------------
extern "C" void kernel_launch(void* const* d_in, const int* in_sizes, int n_in,
                              void* d_out, int out_size)
{
    const int*   train_types    = (const int*)d_in[1];
    const int*   node_neigh     = (const int*)d_in[2];
    const int*   indices        = (const int*)d_in[3];
    const float* user_features  = (const float*)d_in[4];
    const float* text_features  = (const float*)d_in[5];
    const float* neigh_features = (const float*)d_in[6];
    const float* text_embed     = (const float*)d_in[7];
    const float* user_embed     = (const float*)d_in[8];
    const float* tweet_u        = (const float*)d_in[9];
    const float* user_u         = (const float*)d_in[10];
    const float* trans_w        = (const float*)d_in[11];
    const float* s1             = (const float*)d_in[12];
    const float* s2             = (const float*)d_in[13];

    int B  = in_sizes[3];
    int NU = in_sizes[4] / USER_DIM;
    float* out = (float*)d_out;

    const int trans_smem = (2 * TEXT_DIM * EMBU + 32 * 40) * 4 + 32 * 4;
    cudaFuncSetAttribute(k_trans, cudaFuncAttributeMaxDynamicSharedMemorySize,
                         trans_smem);
    const int gemm_smem = GEMM_SMEM_FLOATS * 4;
    cudaFuncSetAttribute(k_gemm5, cudaFuncAttributeMaxDynamicSharedMemorySize,
                         gemm_smem);

    int gwarps = B * 2;
    k_gather<<<(gwarps + 7) / 8, 256>>>(train_types, node_neigh,
                                        neigh_features, B);

    k_scan<<<1, 1024>>>(indices, train_types, B, NU);

    int T = (B + 31) / 32;
    k_trans<<<2 * T, 256, trans_smem>>>(tweet_u, user_u, s1, s2, B, T);

    int utiles = (B + 63) / 64;
    k_gemm5<<<utiles * (1 + NCHUNK), 320, gemm_smem>>>(
        out, indices, user_features, text_features, user_embed,
        text_embed, trans_w, B, NU, utiles);

    k_reduce<<<B, 256>>>(out, B);
}